// round 1
// baseline (speedup 1.0000x reference)
#include <cuda_runtime.h>
#include <math.h>
#include <stdint.h>

#define Tk    1024   // tokens = B*S
#define Hd    1024
#define Fd    3584
#define Ed    8
#define NSLOT 2048   // Tk * top_k
#define BM    64
#define BN    64
#define BK    32
#define MAX_TILES 40

// ---------------- scratch (no allocation allowed) ----------------
__device__ float g_logits[Tk * Ed];
__device__ int   g_tok[NSLOT];
__device__ float g_wt[NSLOT];
__device__ int   g_tile_e[MAX_TILES];
__device__ int   g_tile_row[MAX_TILES];
__device__ int   g_tile_cnt[MAX_TILES];
__device__ int   g_ntiles;
__device__ __align__(16) float g_act[(size_t)NSLOT * Fd];   // ~29 MB

// ---------------- helpers ----------------
__device__ __forceinline__ uint32_t f2tf(float f) {
    uint32_t u;
    asm("cvt.rna.tf32.f32 %0, %1;" : "=r"(u) : "f"(f));
    return u;
}

__device__ __forceinline__ void mma_tf32(float* c, const uint32_t* a, const uint32_t* b) {
    asm volatile(
        "mma.sync.aligned.m16n8k8.row.col.f32.tf32.tf32.f32 "
        "{%0,%1,%2,%3}, {%4,%5,%6,%7}, {%8,%9}, {%0,%1,%2,%3};"
        : "+f"(c[0]), "+f"(c[1]), "+f"(c[2]), "+f"(c[3])
        : "r"(a[0]), "r"(a[1]), "r"(a[2]), "r"(a[3]), "r"(b[0]), "r"(b[1]));
}

// ---------------- zero output ----------------
__global__ void k_zero(float* out) {
    int i = blockIdx.x * blockDim.x + threadIdx.x;   // 1024*256 = 262144 float4 = 1048576 floats
    reinterpret_cast<float4*>(out)[i] = make_float4(0.f, 0.f, 0.f, 0.f);
}

// ---------------- router logits: x @ gate_w^T (fp32 exact) ----------------
__global__ void k_router(const float* __restrict__ x, const float* __restrict__ gw,
                         float* __restrict__ logits_out) {
    int t    = blockIdx.x;
    int wid  = threadIdx.x >> 5;   // expert
    int lane = threadIdx.x & 31;
    const float* xr = x + (size_t)t * Hd;
    const float* gr = gw + (size_t)wid * Hd;
    float acc = 0.f;
    for (int k = lane; k < Hd; k += 32) acc += xr[k] * gr[k];
#pragma unroll
    for (int d = 16; d; d >>= 1) acc += __shfl_down_sync(0xffffffffu, acc, d);
    if (lane == 0) {
        g_logits[t * Ed + wid] = acc;
        if (logits_out) logits_out[t * Ed + wid] = acc;
    }
}

// ---------------- routing: softmax, top-2, stable per-expert compaction ----------------
__global__ void k_route() {
    int t    = threadIdx.x;          // 1024 threads, one per token
    int lane = t & 31;
    int wid  = t >> 5;

    float l[Ed];
    float m = -1e30f;
#pragma unroll
    for (int e = 0; e < Ed; e++) { l[e] = g_logits[t * Ed + e]; m = fmaxf(m, l[e]); }
    float p[Ed]; float s = 0.f;
#pragma unroll
    for (int e = 0; e < Ed; e++) { p[e] = expf(l[e] - m); s += p[e]; }
#pragma unroll
    for (int e = 0; e < Ed; e++) p[e] /= s;

    int i0 = 0; float b0 = p[0];
#pragma unroll
    for (int e = 1; e < Ed; e++) if (p[e] > b0) { b0 = p[e]; i0 = e; }
    int i1 = -1; float b1 = -1.f;
#pragma unroll
    for (int e = 0; e < Ed; e++) if (e != i0 && p[e] > b1) { b1 = p[e]; i1 = e; }
    float inv = 1.f / (b0 + b1);
    float w0 = b0 * inv, w1 = b1 * inv;

    __shared__ int cnt_s[Ed];
    __shared__ int off_s[Ed + 1];
    __shared__ int wsum_s[32];

    if (t < Ed) cnt_s[t] = 0;
    __syncthreads();
    atomicAdd(&cnt_s[i0], 1);
    atomicAdd(&cnt_s[i1], 1);
    __syncthreads();
    if (t == 0) {
        off_s[0] = 0;
        for (int e = 0; e < Ed; e++) off_s[e + 1] = off_s[e] + cnt_s[e];
    }
    __syncthreads();

    for (int e = 0; e < Ed; e++) {
        int p0 = (i0 == e) ? 1 : 0;
        int p1 = (i1 == e) ? 1 : 0;
        int v  = p0 + p1;
        int sc = v;
#pragma unroll
        for (int d = 1; d < 32; d <<= 1) {
            int n = __shfl_up_sync(0xffffffffu, sc, d);
            if (lane >= d) sc += n;
        }
        if (lane == 31) wsum_s[wid] = sc;
        int ex = sc - v;
        __syncthreads();
        if (wid == 0) {
            int sv  = wsum_s[lane];
            int sc2 = sv;
#pragma unroll
            for (int d = 1; d < 32; d <<= 1) {
                int n = __shfl_up_sync(0xffffffffu, sc2, d);
                if (lane >= d) sc2 += n;
            }
            wsum_s[lane] = sc2 - sv;
        }
        __syncthreads();
        int base = off_s[e] + wsum_s[wid] + ex;
        if (p0) { g_tok[base] = t; g_wt[base] = w0; }
        if (p1) { int pp = base + p0; g_tok[pp] = t; g_wt[pp] = w1; }
        __syncthreads();
    }

    if (t == 0) {
        int nt = 0;
        for (int e = 0; e < Ed; e++) {
            int c  = cnt_s[e];
            int st = off_s[e];
            for (int r = 0; r < c; r += BM) {
                g_tile_e[nt]   = e;
                g_tile_row[nt] = st + r;
                g_tile_cnt[nt] = (c - r < BM) ? (c - r) : BM;
                nt++;
            }
        }
        g_ntiles = nt;
    }
}

// ---------------- GEMM1: h1 = Xg @ w1[e]^T, h3 = Xg @ w3[e]^T, act = silu(h1)*h3 ----------------
__global__ __launch_bounds__(128) void k_gemm1(const float* __restrict__ x,
                                               const float* __restrict__ w1,
                                               const float* __restrict__ w3) {
    int tile = blockIdx.y;
    if (tile >= g_ntiles) return;
    int e    = g_tile_e[tile];
    int row0 = g_tile_row[tile];
    int cnt  = g_tile_cnt[tile];
    int nb   = blockIdx.x * BN;

    __shared__ uint32_t As[BM][BK + 1];
    __shared__ uint32_t B1s[BN][BK + 1];
    __shared__ uint32_t B3s[BN][BK + 1];
    __shared__ int toks[BM];

    int tid = threadIdx.x;
    if (tid < BM) {
        int r = row0 + tid;
        if (r > NSLOT - 1) r = NSLOT - 1;
        toks[tid] = g_tok[r];
    }
    __syncthreads();

    const float* w1e = w1 + (size_t)e * Fd * Hd;
    const float* w3e = w3 + (size_t)e * Fd * Hd;

    float acc1[32], acc3[32];
#pragma unroll
    for (int i = 0; i < 32; i++) { acc1[i] = 0.f; acc3[i] = 0.f; }

    int wid = tid >> 5, lane = tid & 31;
    int wm = wid & 1, wn = wid >> 1;
    int g = lane >> 2, tg = lane & 3;

    for (int k0 = 0; k0 < Hd; k0 += BK) {
#pragma unroll
        for (int i = 0; i < 4; i++) {
            int t4 = tid + i * 128;       // 0..511 float4 slots
            int r  = t4 >> 3;             // 8 float4 per row
            int c  = (t4 & 7) * 4;
            float4 av = *reinterpret_cast<const float4*>(x + (size_t)toks[r] * Hd + k0 + c);
            As[r][c] = f2tf(av.x); As[r][c + 1] = f2tf(av.y);
            As[r][c + 2] = f2tf(av.z); As[r][c + 3] = f2tf(av.w);
            float4 b1v = *reinterpret_cast<const float4*>(w1e + (size_t)(nb + r) * Hd + k0 + c);
            B1s[r][c] = f2tf(b1v.x); B1s[r][c + 1] = f2tf(b1v.y);
            B1s[r][c + 2] = f2tf(b1v.z); B1s[r][c + 3] = f2tf(b1v.w);
            float4 b3v = *reinterpret_cast<const float4*>(w3e + (size_t)(nb + r) * Hd + k0 + c);
            B3s[r][c] = f2tf(b3v.x); B3s[r][c + 1] = f2tf(b3v.y);
            B3s[r][c + 2] = f2tf(b3v.z); B3s[r][c + 3] = f2tf(b3v.w);
        }
        __syncthreads();
#pragma unroll
        for (int kk = 0; kk < BK; kk += 8) {
            uint32_t a[2][4];
#pragma unroll
            for (int mt = 0; mt < 2; mt++) {
                int mr = wm * 32 + mt * 16;
                a[mt][0] = As[mr + g][kk + tg];
                a[mt][1] = As[mr + g + 8][kk + tg];
                a[mt][2] = As[mr + g][kk + tg + 4];
                a[mt][3] = As[mr + g + 8][kk + tg + 4];
            }
#pragma unroll
            for (int nt = 0; nt < 4; nt++) {
                int nr = wn * 32 + nt * 8;
                uint32_t b1f[2] = { B1s[nr + g][kk + tg], B1s[nr + g][kk + tg + 4] };
                uint32_t b3f[2] = { B3s[nr + g][kk + tg], B3s[nr + g][kk + tg + 4] };
#pragma unroll
                for (int mt = 0; mt < 2; mt++) {
                    mma_tf32(&acc1[(mt * 4 + nt) * 4], a[mt], b1f);
                    mma_tf32(&acc3[(mt * 4 + nt) * 4], a[mt], b3f);
                }
            }
        }
        __syncthreads();
    }

#pragma unroll
    for (int mt = 0; mt < 2; mt++)
#pragma unroll
        for (int nt = 0; nt < 4; nt++)
#pragma unroll
            for (int c = 0; c < 4; c++) {
                int rloc = wm * 32 + mt * 16 + g + ((c >> 1) ? 8 : 0);
                if (rloc < cnt) {
                    int col = nb + wn * 32 + nt * 8 + tg * 2 + (c & 1);
                    float h1 = acc1[(mt * 4 + nt) * 4 + c];
                    float h3 = acc3[(mt * 4 + nt) * 4 + c];
                    float sv = h1 / (1.f + expf(-h1));
                    g_act[(size_t)(row0 + rloc) * Fd + col] = sv * h3;
                }
            }
}

// ---------------- GEMM2: y = act @ w2[e]^T, out[token] += weight * y ----------------
__global__ __launch_bounds__(128) void k_gemm2(const float* __restrict__ w2,
                                               float* __restrict__ out) {
    int tile = blockIdx.y;
    if (tile >= g_ntiles) return;
    int e    = g_tile_e[tile];
    int row0 = g_tile_row[tile];
    int cnt  = g_tile_cnt[tile];
    int nb   = blockIdx.x * BN;

    __shared__ uint32_t As[BM][BK + 1];
    __shared__ uint32_t Bs[BN][BK + 1];

    int tid = threadIdx.x;
    const float* w2e = w2 + (size_t)e * Hd * Fd;

    float acc[32];
#pragma unroll
    for (int i = 0; i < 32; i++) acc[i] = 0.f;

    int wid = tid >> 5, lane = tid & 31;
    int wm = wid & 1, wn = wid >> 1;
    int g = lane >> 2, tg = lane & 3;

    for (int k0 = 0; k0 < Fd; k0 += BK) {
#pragma unroll
        for (int i = 0; i < 4; i++) {
            int t4 = tid + i * 128;
            int r  = t4 >> 3;
            int c  = (t4 & 7) * 4;
            int rg = row0 + r; if (rg > NSLOT - 1) rg = NSLOT - 1;
            float4 av = *reinterpret_cast<const float4*>(g_act + (size_t)rg * Fd + k0 + c);
            As[r][c] = f2tf(av.x); As[r][c + 1] = f2tf(av.y);
            As[r][c + 2] = f2tf(av.z); As[r][c + 3] = f2tf(av.w);
            float4 bv = *reinterpret_cast<const float4*>(w2e + (size_t)(nb + r) * Fd + k0 + c);
            Bs[r][c] = f2tf(bv.x); Bs[r][c + 1] = f2tf(bv.y);
            Bs[r][c + 2] = f2tf(bv.z); Bs[r][c + 3] = f2tf(bv.w);
        }
        __syncthreads();
#pragma unroll
        for (int kk = 0; kk < BK; kk += 8) {
            uint32_t a[2][4];
#pragma unroll
            for (int mt = 0; mt < 2; mt++) {
                int mr = wm * 32 + mt * 16;
                a[mt][0] = As[mr + g][kk + tg];
                a[mt][1] = As[mr + g + 8][kk + tg];
                a[mt][2] = As[mr + g][kk + tg + 4];
                a[mt][3] = As[mr + g + 8][kk + tg + 4];
            }
#pragma unroll
            for (int nt = 0; nt < 4; nt++) {
                int nr = wn * 32 + nt * 8;
                uint32_t bf[2] = { Bs[nr + g][kk + tg], Bs[nr + g][kk + tg + 4] };
#pragma unroll
                for (int mt = 0; mt < 2; mt++)
                    mma_tf32(&acc[(mt * 4 + nt) * 4], a[mt], bf);
            }
        }
        __syncthreads();
    }

#pragma unroll
    for (int mt = 0; mt < 2; mt++)
#pragma unroll
        for (int nt = 0; nt < 4; nt++)
#pragma unroll
            for (int c = 0; c < 4; c++) {
                int rloc = wm * 32 + mt * 16 + g + ((c >> 1) ? 8 : 0);
                if (rloc < cnt) {
                    int slot = row0 + rloc;
                    int col  = nb + wn * 32 + nt * 8 + tg * 2 + (c & 1);
                    int tok  = g_tok[slot];
                    float v  = acc[(mt * 4 + nt) * 4 + c] * g_wt[slot];
                    atomicAdd(&out[(size_t)tok * Hd + col], v);  // exactly 2 adds/elem: deterministic
                }
            }
}

// ---------------- launch ----------------
extern "C" void kernel_launch(void* const* d_in, const int* in_sizes, int n_in,
                              void* d_out, int out_size) {
    const float* x  = (const float*)d_in[0];   // hidden_states [2,512,1024]
    const float* gw = (const float*)d_in[1];   // gate_w [8,1024]
    const float* w1 = (const float*)d_in[2];   // [8,3584,1024]
    const float* w2 = (const float*)d_in[3];   // [8,1024,3584]
    const float* w3 = (const float*)d_in[4];   // [8,3584,1024]
    float* out = (float*)d_out;

    const int main_elems = Tk * Hd;            // 1048576
    float* logits_out = (out_size >= main_elems + Tk * Ed) ? (out + main_elems) : nullptr;

    k_zero<<<1024, 256>>>(out);
    k_router<<<Tk, 256>>>(x, gw, logits_out);
    k_route<<<1, 1024>>>();
    k_gemm1<<<dim3(Fd / BN, MAX_TILES), 128>>>(x, w1, w3);
    k_gemm2<<<dim3(Hd / BN, MAX_TILES), 128>>>(w2, out);
}

// round 2
// speedup vs baseline: 1.9167x; 1.9167x over previous
#include <cuda_runtime.h>
#include <math.h>
#include <stdint.h>

#define Tk    1024   // tokens = B*S
#define Hd    1024
#define Fd    3584
#define Ed    8
#define NSLOT 2048   // Tk * top_k
#define BM    64
#define BN    64
#define MAX_TILES 40

// ---------------- scratch (no allocation allowed) ----------------
__device__ float g_logits[Tk * Ed];
__device__ int   g_tok[NSLOT];
__device__ float g_wt[NSLOT];
__device__ int   g_tile_e[MAX_TILES];
__device__ int   g_tile_row[MAX_TILES];
__device__ int   g_tile_cnt[MAX_TILES];
__device__ int   g_ntiles;
__device__ __align__(16) float g_act[(size_t)NSLOT * Fd];   // ~29 MB

// ---------------- helpers ----------------
__device__ __forceinline__ uint32_t f2tf(float f) {
    uint32_t u;
    asm("cvt.rna.tf32.f32 %0, %1;" : "=r"(u) : "f"(f));
    return u;
}

__device__ __forceinline__ void mma_tf32(float* c, const uint32_t* a, const uint32_t* b) {
    asm volatile(
        "mma.sync.aligned.m16n8k8.row.col.f32.tf32.tf32.f32 "
        "{%0,%1,%2,%3}, {%4,%5,%6,%7}, {%8,%9}, {%0,%1,%2,%3};"
        : "+f"(c[0]), "+f"(c[1]), "+f"(c[2]), "+f"(c[3])
        : "r"(a[0]), "r"(a[1]), "r"(a[2]), "r"(a[3]), "r"(b[0]), "r"(b[1]));
}

// ---------------- zero output ----------------
__global__ void k_zero(float* out) {
    int i = blockIdx.x * blockDim.x + threadIdx.x;
    reinterpret_cast<float4*>(out)[i] = make_float4(0.f, 0.f, 0.f, 0.f);
}

// ---------------- router logits: x @ gate_w^T (fp32 exact) ----------------
__global__ void k_router(const float* __restrict__ x, const float* __restrict__ gw,
                         float* __restrict__ logits_out) {
    int t    = blockIdx.x;
    int wid  = threadIdx.x >> 5;   // expert
    int lane = threadIdx.x & 31;
    const float* xr = x + (size_t)t * Hd;
    const float* gr = gw + (size_t)wid * Hd;
    float acc = 0.f;
    for (int k = lane; k < Hd; k += 32) acc += xr[k] * gr[k];
#pragma unroll
    for (int d = 16; d; d >>= 1) acc += __shfl_down_sync(0xffffffffu, acc, d);
    if (lane == 0) {
        g_logits[t * Ed + wid] = acc;
        if (logits_out) logits_out[t * Ed + wid] = acc;
    }
}

// ---------------- routing: softmax, top-2, stable per-expert compaction ----------------
__global__ void k_route() {
    int t    = threadIdx.x;          // 1024 threads, one per token
    int lane = t & 31;
    int wid  = t >> 5;

    float l[Ed];
    float m = -1e30f;
#pragma unroll
    for (int e = 0; e < Ed; e++) { l[e] = g_logits[t * Ed + e]; m = fmaxf(m, l[e]); }
    float p[Ed]; float s = 0.f;
#pragma unroll
    for (int e = 0; e < Ed; e++) { p[e] = expf(l[e] - m); s += p[e]; }
#pragma unroll
    for (int e = 0; e < Ed; e++) p[e] /= s;

    int i0 = 0; float b0 = p[0];
#pragma unroll
    for (int e = 1; e < Ed; e++) if (p[e] > b0) { b0 = p[e]; i0 = e; }
    int i1 = -1; float b1 = -1.f;
#pragma unroll
    for (int e = 0; e < Ed; e++) if (e != i0 && p[e] > b1) { b1 = p[e]; i1 = e; }
    float inv = 1.f / (b0 + b1);
    float w0 = b0 * inv, w1 = b1 * inv;

    __shared__ int cnt_s[Ed];
    __shared__ int off_s[Ed + 1];
    __shared__ int wsum_s[32];

    if (t < Ed) cnt_s[t] = 0;
    __syncthreads();
    atomicAdd(&cnt_s[i0], 1);
    atomicAdd(&cnt_s[i1], 1);
    __syncthreads();
    if (t == 0) {
        off_s[0] = 0;
        for (int e = 0; e < Ed; e++) off_s[e + 1] = off_s[e] + cnt_s[e];
    }
    __syncthreads();

    for (int e = 0; e < Ed; e++) {
        int p0 = (i0 == e) ? 1 : 0;
        int p1 = (i1 == e) ? 1 : 0;
        int v  = p0 + p1;
        int sc = v;
#pragma unroll
        for (int d = 1; d < 32; d <<= 1) {
            int n = __shfl_up_sync(0xffffffffu, sc, d);
            if (lane >= d) sc += n;
        }
        if (lane == 31) wsum_s[wid] = sc;
        int ex = sc - v;
        __syncthreads();
        if (wid == 0) {
            int sv  = wsum_s[lane];
            int sc2 = sv;
#pragma unroll
            for (int d = 1; d < 32; d <<= 1) {
                int n = __shfl_up_sync(0xffffffffu, sc2, d);
                if (lane >= d) sc2 += n;
            }
            wsum_s[lane] = sc2 - sv;
        }
        __syncthreads();
        int base = off_s[e] + wsum_s[wid] + ex;
        if (p0) { g_tok[base] = t; g_wt[base] = w0; }
        if (p1) { int pp = base + p0; g_tok[pp] = t; g_wt[pp] = w1; }
        __syncthreads();
    }

    if (t == 0) {
        int nt = 0;
        for (int e = 0; e < Ed; e++) {
            int c  = cnt_s[e];
            int st = off_s[e];
            for (int r = 0; r < c; r += BM) {
                g_tile_e[nt]   = e;
                g_tile_row[nt] = st + r;
                g_tile_cnt[nt] = (c - r < BM) ? (c - r) : BM;
                nt++;
            }
        }
        g_ntiles = nt;
    }
}

// Fragment-major smem layout:
//   A block (16 rows x 8 k) = 132 words: word = blk*132 + lane*4 + reg,
//     reg = hm + 2*hk  (hm = row-within-16 / 8, hk = (k%8)/4), lane = g*4+tg.
//   B block (8 n x 8 k)     =  66 words: word = blk*66 + lane*2 + hk.
// Consumer: A = one LDS.128, B = one LDS.64, both conflict-free.

// ---------------- GEMM1: act = silu(Xg @ w1^T) * (Xg @ w3^T) ----------------
// chunk = 16 k-cols, double buffered. smem per buffer: A 1056 + B1 1056 + B3 1056 words.
__global__ __launch_bounds__(128, 3) void k_gemm1(const float* __restrict__ x,
                                                  const float* __restrict__ w1,
                                                  const float* __restrict__ w3) {
    int tile = blockIdx.y;
    if (tile >= g_ntiles) return;
    int e    = g_tile_e[tile];
    int row0 = g_tile_row[tile];
    int cnt  = g_tile_cnt[tile];
    int nb   = blockIdx.x * BN;

    __shared__ uint32_t sm[2][3168];
    __shared__ int toks[BM];

    int tid = threadIdx.x;
    if (tid < BM) {
        int r = row0 + tid;
        if (r > NSLOT - 1) r = NSLOT - 1;
        toks[tid] = g_tok[r];
    }
    __syncthreads();

    const float* w1e = w1 + (size_t)e * Fd * Hd;
    const float* w3e = w3 + (size_t)e * Fd * Hd;

    float acc1[32], acc3[32];
#pragma unroll
    for (int i = 0; i < 32; i++) { acc1[i] = 0.f; acc3[i] = 0.f; }

    int wid = tid >> 5, lane = tid & 31;
    int wm = wid & 1, wn = wid >> 1;
    int g = lane >> 2, tg = lane & 3;

    // loader indices: idx = tid + 128*j, j=0..1; r = idx>>2 (row), q = idx&3 (float4 col)
    const int rl = tid >> 2;     // 0..31 (j=0); +32 for j=1
    const int q  = tid & 3;
    const int kk2q = q >> 1, hk = q & 1;

    // precomputed store bases (word offsets within a buffer)
    int sbA[2], sbB[2];
#pragma unroll
    for (int j = 0; j < 2; j++) {
        int r  = rl + 32 * j;
        int m16 = r >> 4, rr = r & 15, gg = rr & 7, hm = rr >> 3;
        sbA[j] = (m16 * 2 + kk2q) * 132 + gg * 16 + hm + 2 * hk;
        int n8 = r >> 3, gb = r & 7;
        sbB[j] = (n8 * 2 + kk2q) * 66 + gb * 8 + hk;
    }

    float4 ra[2], rb1[2], rb3[2];
    const int kcol = q * 4;

    // preload chunk 0
#pragma unroll
    for (int j = 0; j < 2; j++) {
        int r = rl + 32 * j;
        ra[j]  = *reinterpret_cast<const float4*>(x   + (size_t)toks[r] * Hd + kcol);
        rb1[j] = *reinterpret_cast<const float4*>(w1e + (size_t)(nb + r) * Hd + kcol);
        rb3[j] = *reinterpret_cast<const float4*>(w3e + (size_t)(nb + r) * Hd + kcol);
    }

    const int NC = Hd / 16;   // 64 chunks
    for (int c = 0; c < NC; c++) {
        int buf = c & 1;
        uint32_t* sA  = sm[buf];
        uint32_t* sB1 = sm[buf] + 1056;
        uint32_t* sB3 = sm[buf] + 2112;
        // scatter-store current chunk (cvt to tf32)
#pragma unroll
        for (int j = 0; j < 2; j++) {
            sA[sbA[j]]      = f2tf(ra[j].x);
            sA[sbA[j] + 4]  = f2tf(ra[j].y);
            sA[sbA[j] + 8]  = f2tf(ra[j].z);
            sA[sbA[j] + 12] = f2tf(ra[j].w);
            sB1[sbB[j]]     = f2tf(rb1[j].x);
            sB1[sbB[j] + 2] = f2tf(rb1[j].y);
            sB1[sbB[j] + 4] = f2tf(rb1[j].z);
            sB1[sbB[j] + 6] = f2tf(rb1[j].w);
            sB3[sbB[j]]     = f2tf(rb3[j].x);
            sB3[sbB[j] + 2] = f2tf(rb3[j].y);
            sB3[sbB[j] + 4] = f2tf(rb3[j].z);
            sB3[sbB[j] + 6] = f2tf(rb3[j].w);
        }
        // prefetch next chunk
        if (c + 1 < NC) {
            int kb = (c + 1) * 16 + kcol;
#pragma unroll
            for (int j = 0; j < 2; j++) {
                int r = rl + 32 * j;
                ra[j]  = *reinterpret_cast<const float4*>(x   + (size_t)toks[r] * Hd + kb);
                rb1[j] = *reinterpret_cast<const float4*>(w1e + (size_t)(nb + r) * Hd + kb);
                rb3[j] = *reinterpret_cast<const float4*>(w3e + (size_t)(nb + r) * Hd + kb);
            }
        }
        __syncthreads();
        // compute on current buffer: kk2 = 0,1
#pragma unroll
        for (int kk2 = 0; kk2 < 2; kk2++) {
            uint4 a0 = *reinterpret_cast<uint4*>(&sA[((wm * 2 + 0) * 2 + kk2) * 132 + lane * 4]);
            uint4 a1 = *reinterpret_cast<uint4*>(&sA[((wm * 2 + 1) * 2 + kk2) * 132 + lane * 4]);
#pragma unroll
            for (int nt = 0; nt < 4; nt++) {
                int bo = ((wn * 4 + nt) * 2 + kk2) * 66 + lane * 2;
                uint2 b1v = *reinterpret_cast<uint2*>(&sB1[bo]);
                uint2 b3v = *reinterpret_cast<uint2*>(&sB3[bo]);
                uint32_t b1f[2] = { b1v.x, b1v.y };
                uint32_t b3f[2] = { b3v.x, b3v.y };
                mma_tf32(&acc1[(0 * 4 + nt) * 4], reinterpret_cast<uint32_t*>(&a0), b1f);
                mma_tf32(&acc1[(1 * 4 + nt) * 4], reinterpret_cast<uint32_t*>(&a1), b1f);
                mma_tf32(&acc3[(0 * 4 + nt) * 4], reinterpret_cast<uint32_t*>(&a0), b3f);
                mma_tf32(&acc3[(1 * 4 + nt) * 4], reinterpret_cast<uint32_t*>(&a1), b3f);
            }
        }
        __syncthreads();
    }

#pragma unroll
    for (int mt = 0; mt < 2; mt++)
#pragma unroll
        for (int nt = 0; nt < 4; nt++)
#pragma unroll
            for (int c = 0; c < 4; c++) {
                int rloc = wm * 32 + mt * 16 + g + ((c >> 1) ? 8 : 0);
                if (rloc < cnt) {
                    int col = nb + wn * 32 + nt * 8 + tg * 2 + (c & 1);
                    float h1 = acc1[(mt * 4 + nt) * 4 + c];
                    float h3 = acc3[(mt * 4 + nt) * 4 + c];
                    float sv = h1 / (1.f + expf(-h1));
                    g_act[(size_t)(row0 + rloc) * Fd + col] = sv * h3;
                }
            }
}

// ---------------- GEMM2: out[token] += weight * (act @ w2^T) ----------------
// chunk = 32 k-cols, double buffered. smem per buffer: A 2112 + B 2112 words.
__global__ __launch_bounds__(128, 4) void k_gemm2(const float* __restrict__ w2,
                                                  float* __restrict__ out) {
    int tile = blockIdx.y;
    if (tile >= g_ntiles) return;
    int e    = g_tile_e[tile];
    int row0 = g_tile_row[tile];
    int cnt  = g_tile_cnt[tile];
    int nb   = blockIdx.x * BN;

    __shared__ uint32_t sm[2][4224];

    int tid = threadIdx.x;
    const float* w2e = w2 + (size_t)e * Hd * Fd;

    float acc[32];
#pragma unroll
    for (int i = 0; i < 32; i++) acc[i] = 0.f;

    int wid = tid >> 5, lane = tid & 31;
    int wm = wid & 1, wn = wid >> 1;
    int g = lane >> 2, tg = lane & 3;

    // loader: idx = tid + 128*j, j=0..3; r = idx>>3 (row), q = idx&7 (float4 col of 8)
    const int rl = tid >> 3;    // 0..15 (j=0); +16 per j
    const int q  = tid & 7;
    const int kkq = q >> 1, hk = q & 1;
    const int kcol = q * 4;

    int sbA[4], sbB[4], rowA[4];
#pragma unroll
    for (int j = 0; j < 4; j++) {
        int r  = rl + 16 * j;
        int m16 = r >> 4, rr = r & 15, gg = rr & 7, hm = rr >> 3;
        sbA[j] = (m16 * 4 + kkq) * 132 + gg * 16 + hm + 2 * hk;
        int n8 = r >> 3, gb = r & 7;
        sbB[j] = (n8 * 4 + kkq) * 66 + gb * 8 + hk;
        int rg = row0 + r; if (rg > NSLOT - 1) rg = NSLOT - 1;
        rowA[j] = rg;
    }

    float4 ra[4], rb[4];
#pragma unroll
    for (int j = 0; j < 4; j++) {
        int r = rl + 16 * j;
        ra[j] = *reinterpret_cast<const float4*>(g_act + (size_t)rowA[j] * Fd + kcol);
        rb[j] = *reinterpret_cast<const float4*>(w2e + (size_t)(nb + r) * Fd + kcol);
    }

    const int NC = Fd / 32;   // 112 chunks
    for (int c = 0; c < NC; c++) {
        int buf = c & 1;
        uint32_t* sA = sm[buf];
        uint32_t* sB = sm[buf] + 2112;
#pragma unroll
        for (int j = 0; j < 4; j++) {
            sA[sbA[j]]      = f2tf(ra[j].x);
            sA[sbA[j] + 4]  = f2tf(ra[j].y);
            sA[sbA[j] + 8]  = f2tf(ra[j].z);
            sA[sbA[j] + 12] = f2tf(ra[j].w);
            sB[sbB[j]]     = f2tf(rb[j].x);
            sB[sbB[j] + 2] = f2tf(rb[j].y);
            sB[sbB[j] + 4] = f2tf(rb[j].z);
            sB[sbB[j] + 6] = f2tf(rb[j].w);
        }
        if (c + 1 < NC) {
            int kb = (c + 1) * 32 + kcol;
#pragma unroll
            for (int j = 0; j < 4; j++) {
                int r = rl + 16 * j;
                ra[j] = *reinterpret_cast<const float4*>(g_act + (size_t)rowA[j] * Fd + kb);
                rb[j] = *reinterpret_cast<const float4*>(w2e + (size_t)(nb + r) * Fd + kb);
            }
        }
        __syncthreads();
#pragma unroll
        for (int kk = 0; kk < 4; kk++) {
            uint4 a0 = *reinterpret_cast<uint4*>(&sA[((wm * 2 + 0) * 4 + kk) * 132 + lane * 4]);
            uint4 a1 = *reinterpret_cast<uint4*>(&sA[((wm * 2 + 1) * 4 + kk) * 132 + lane * 4]);
#pragma unroll
            for (int nt = 0; nt < 4; nt++) {
                int bo = ((wn * 4 + nt) * 4 + kk) * 66 + lane * 2;
                uint2 bv = *reinterpret_cast<uint2*>(&sB[bo]);
                uint32_t bf[2] = { bv.x, bv.y };
                mma_tf32(&acc[(0 * 4 + nt) * 4], reinterpret_cast<uint32_t*>(&a0), bf);
                mma_tf32(&acc[(1 * 4 + nt) * 4], reinterpret_cast<uint32_t*>(&a1), bf);
            }
        }
        __syncthreads();
    }

#pragma unroll
    for (int mt = 0; mt < 2; mt++)
#pragma unroll
        for (int nt = 0; nt < 4; nt++)
#pragma unroll
            for (int c = 0; c < 4; c++) {
                int rloc = wm * 32 + mt * 16 + g + ((c >> 1) ? 8 : 0);
                if (rloc < cnt) {
                    int slot = row0 + rloc;
                    int col  = nb + wn * 32 + nt * 8 + tg * 2 + (c & 1);
                    int tok  = g_tok[slot];
                    float v  = acc[(mt * 4 + nt) * 4 + c] * g_wt[slot];
                    atomicAdd(&out[(size_t)tok * Hd + col], v);  // exactly 2 adds/elem: deterministic
                }
            }
}

// ---------------- launch ----------------
extern "C" void kernel_launch(void* const* d_in, const int* in_sizes, int n_in,
                              void* d_out, int out_size) {
    const float* x  = (const float*)d_in[0];   // hidden_states [2,512,1024]
    const float* gw = (const float*)d_in[1];   // gate_w [8,1024]
    const float* w1 = (const float*)d_in[2];   // [8,3584,1024]
    const float* w2 = (const float*)d_in[3];   // [8,1024,3584]
    const float* w3 = (const float*)d_in[4];   // [8,3584,1024]
    float* out = (float*)d_out;

    const int main_elems = Tk * Hd;            // 1048576
    float* logits_out = (out_size >= main_elems + Tk * Ed) ? (out + main_elems) : nullptr;

    k_zero<<<1024, 256>>>(out);
    k_router<<<Tk, 256>>>(x, gw, logits_out);
    k_route<<<1, 1024>>>();
    k_gemm1<<<dim3(Fd / BN, MAX_TILES), 128>>>(x, w1, w3);
    k_gemm2<<<dim3(Hd / BN, MAX_TILES), 128>>>(w2, out);
}